// round 10
// baseline (speedup 1.0000x reference)
#include <cuda_runtime.h>
#include <cuda_bf16.h>

// Problem constants
#define NUM_CW   512
#define CDIM     64
#define N_IMG    32
#define HWSZ     4096            // 64*64
#define T_TOK    (N_IMG * HWSZ)  // 131072 tokens
#define GAMMA_F  0.99f

// Tiling
#define BM       128             // tokens per block
#define BN       32              // codewords per chunk
#define N_CHUNK  (NUM_CW / BN)   // 16
#define TM       8               // tokens per thread (4 f32x2 pairs)
#define TN       4               // codewords per thread
#define NTHR     128             // (BM/TM)*(BN/TN) = 16*8

// Output layout: q | codebook_new | N_new | m_new
#define OFF_Q   0
#define OFF_CB  (N_IMG * CDIM * HWSZ)          // 8388608
#define OFF_N   (OFF_CB + NUM_CW * CDIM)       // 8421376
#define OFF_M   (OFF_N + NUM_CW)               // 8421888

// Scratch (device globals; zeroed at load, re-zeroed by finalize each call)
__device__ float g_counts[NUM_CW];
__device__ float g_sums[NUM_CW * CDIM];
__device__ float g_cnorm[NUM_CW];
// Transposed codebook with each value duplicated into an f32x2 lane pair:
// g_cbT2[c*NUM_CW + k] = (v, v)
__device__ unsigned long long g_cbT2[CDIM * NUM_CW];

#define FMA_F32X2(acc, a, b) \
    asm("fma.rn.f32x2 %0, %1, %2, %0;" : "+l"(acc) : "l"(a), "l"(b))
#define PACK2(out, lo, hi) \
    asm("mov.b64 %0, {%1, %2};" : "=l"(out) : "f"(lo), "f"(hi))
#define UNPACK2(lo, hi, in) \
    asm("mov.b64 {%0, %1}, %2;" : "=f"(lo), "=f"(hi) : "l"(in))

// Norms (warp-shuffle + atomic) and duplicated-transpose build.
__global__ void init_kernel(const float* __restrict__ codebook) {
    int i = blockIdx.x * blockDim.x + threadIdx.x;  // 0 .. 32767
    float v = codebook[i];
    int k = i >> 6, c = i & 63;
    unsigned long long d;
    PACK2(d, v, v);
    g_cbT2[c * NUM_CW + k] = d;
    float s = v * v;
#pragma unroll
    for (int off = 16; off > 0; off >>= 1)
        s += __shfl_down_sync(0xFFFFFFFFu, s, off);
    if ((threadIdx.x & 31) == 0)
        atomicAdd(&g_cnorm[k], s);
}

// SGEMM-style tiling; codebook tile pre-duplicated so the inner loop is
// pure LDS.128 + FFMA2 (no packing). 4 CTAs/SM (48 KB smem).
__global__ __launch_bounds__(NTHR)
void assign_kernel(const float* __restrict__ x,
                   const float* __restrict__ codebook,
                   float* __restrict__ out) {
    __shared__ __align__(16) float xs[CDIM][BM];                 // 32 KB
    __shared__ __align__(16) unsigned long long cs2[CDIM][BN];   // 16 KB

    const int tid = threadIdx.x;
    const int tx  = tid & 7;          // codeword group 0..7
    const int ty  = tid >> 3;         // token group 0..15
    const int txh = tx >> 2;          // swizzle bit
    const int t0  = blockIdx.x * BM;  // first token of block
    const int n   = t0 >> 12;
    const int hw0 = t0 & (HWSZ - 1);
    const long base = (long)n * (CDIM * HWSZ) + hw0;

    // Load x tile: 64 rows of 128 floats, each row contiguous in gmem.
    {
        const float* xsrc = x + base;
#pragma unroll
        for (int i = 0; i < (CDIM * BM / 4) / NTHR; i++) {   // 16 iters
            int idx = tid + i * NTHR;
            int c = idx >> 5, q4 = idx & 31;
            float4 v = *(const float4*)(xsrc + c * HWSZ + q4 * 4);
            *(float4*)&xs[c][q4 * 4] = v;
        }
    }

    float best_d[TM];
    int   best_k[TM];
#pragma unroll
    for (int m = 0; m < TM; m++) { best_d[m] = 3.4e38f; best_k[m] = 0; }

    for (int ch = 0; ch < N_CHUNK; ch++) {
        __syncthreads();
        // Load duplicated codebook chunk with bank-conflict swizzle.
        // Logical (txg, q) pair slot stored at txg*2 + ((q + (txg>>2)) & 1).
        {
            const ulonglong2* src = (const ulonglong2*)g_cbT2;  // [c][256]
            ulonglong2* dst = (ulonglong2*)cs2;                 // [c][16]
#pragma unroll
            for (int i = 0; i < (CDIM * BN / 2) / NTHR; i++) {  // 8 iters
                int idx = tid + i * NTHR;      // 0..1023
                int c = idx >> 4, pos = idx & 15;
                int txg = pos >> 1, q = pos & 1;
                dst[c * 16 + txg * 2 + ((q + (txg >> 2)) & 1)] =
                    src[c * 256 + ch * 16 + pos];
            }
        }
        __syncthreads();

        unsigned long long acc[TM / 2][TN];
#pragma unroll
        for (int p = 0; p < TM / 2; p++)
#pragma unroll
            for (int j = 0; j < TN; j++) acc[p][j] = 0ULL;

#pragma unroll 2
        for (int c = 0; c < CDIM; c++) {
            const ulonglong2* xrow = (const ulonglong2*)&xs[c][ty * TM];
            ulonglong2 xA = xrow[0];   // token pairs (0,1),(2,3)
            ulonglong2 xB = xrow[1];   // token pairs (4,5),(6,7)
            const ulonglong2* crow = (const ulonglong2*)&cs2[c][0];
            ulonglong2 cp0 = crow[tx * 2 + ((0 + txh) & 1)];  // dup cw 0,1
            ulonglong2 cp1 = crow[tx * 2 + ((1 + txh) & 1)];  // dup cw 2,3
            FMA_F32X2(acc[0][0], xA.x, cp0.x);
            FMA_F32X2(acc[0][1], xA.x, cp0.y);
            FMA_F32X2(acc[0][2], xA.x, cp1.x);
            FMA_F32X2(acc[0][3], xA.x, cp1.y);
            FMA_F32X2(acc[1][0], xA.y, cp0.x);
            FMA_F32X2(acc[1][1], xA.y, cp0.y);
            FMA_F32X2(acc[1][2], xA.y, cp1.x);
            FMA_F32X2(acc[1][3], xA.y, cp1.y);
            FMA_F32X2(acc[2][0], xB.x, cp0.x);
            FMA_F32X2(acc[2][1], xB.x, cp0.y);
            FMA_F32X2(acc[2][2], xB.x, cp1.x);
            FMA_F32X2(acc[2][3], xB.x, cp1.y);
            FMA_F32X2(acc[3][0], xB.y, cp0.x);
            FMA_F32X2(acc[3][1], xB.y, cp0.y);
            FMA_F32X2(acc[3][2], xB.y, cp1.x);
            FMA_F32X2(acc[3][3], xB.y, cp1.y);
        }

        // Update per-token argmin over this chunk's TN codewords.
        int k0 = ch * BN + tx * TN;
#pragma unroll
        for (int j = 0; j < TN; j++) {
            float nrm = __ldg(&g_cnorm[k0 + j]);
#pragma unroll
            for (int p = 0; p < TM / 2; p++) {
                float lo, hi;
                UNPACK2(lo, hi, acc[p][j]);
                float d0 = fmaf(-2.0f, lo, nrm);
                float d1 = fmaf(-2.0f, hi, nrm);
                if (d0 < best_d[2 * p])     { best_d[2 * p] = d0;     best_k[2 * p] = k0 + j; }
                if (d1 < best_d[2 * p + 1]) { best_d[2 * p + 1] = d1; best_k[2 * p + 1] = k0 + j; }
            }
        }
    }

    // Cross-tx argmin reduction via packed keys in smem (alias cs2).
    __syncthreads();
    unsigned long long* sred = (unsigned long long*)cs2;  // [BM][8] = 8 KB
#pragma unroll
    for (int m = 0; m < TM; m++) {
        unsigned int u = __float_as_uint(best_d[m]);
        u = (u & 0x80000000u) ? ~u : (u | 0x80000000u);   // order-preserving
        sred[(ty * TM + m) * 8 + tx] =
            ((unsigned long long)u << 32) | (unsigned int)best_k[m];
    }
    __syncthreads();

    // One thread per token: finish argmin, write q, EMA atomics.
    {
        const int tok = tid;   // 0..127
        unsigned long long best = sred[tok * 8];
#pragma unroll
        for (int i = 1; i < 8; i++) {
            unsigned long long v = sred[tok * 8 + i];
            if (v < best) best = v;
        }
        int bk = (int)(best & 0xFFFFFFFFu);

        atomicAdd(&g_counts[bk], 1.0f);
        const float4* cw4 = (const float4*)(codebook + bk * CDIM);
        float* qo = out + OFF_Q + base + tok;
        float* sums = &g_sums[bk * CDIM];
#pragma unroll
        for (int i = 0; i < CDIM / 4; i++) {
            float4 v = cw4[i];
            qo[(4 * i + 0) * HWSZ] = v.x;
            qo[(4 * i + 1) * HWSZ] = v.y;
            qo[(4 * i + 2) * HWSZ] = v.z;
            qo[(4 * i + 3) * HWSZ] = v.w;
        }
#pragma unroll
        for (int c = 0; c < CDIM; c++)
            atomicAdd(&sums[c], xs[c][tok]);
    }
}

// One thread per (k, c). Also resets scratch for the next call.
__global__ void finalize_kernel(const float* __restrict__ N_state,
                                const float* __restrict__ m_state,
                                float* __restrict__ out) {
    int i = blockIdx.x * blockDim.x + threadIdx.x;
    if (i >= NUM_CW * CDIM) return;
    int k = i / CDIM;
    float cnt = g_counts[k];
    bool occ = cnt > 0.0f;
    float Nold = N_state[k];
    float Nn = occ ? (Nold * GAMMA_F + cnt * (1.0f - GAMMA_F)) : Nold;
    float mold = m_state[i];
    float mn = occ ? (mold * GAMMA_F + g_sums[i] * (1.0f - GAMMA_F)) : mold;
    out[OFF_M + i]  = mn;
    out[OFF_CB + i] = mn / Nn;
    g_sums[i] = 0.0f;
    if ((i % CDIM) == 0) out[OFF_N + k] = Nn;
    if (i < NUM_CW) { g_counts[i] = 0.0f; g_cnorm[i] = 0.0f; }
}

extern "C" void kernel_launch(void* const* d_in, const int* in_sizes, int n_in,
                              void* d_out, int out_size) {
    const float* x        = (const float*)d_in[0];
    const float* codebook = (const float*)d_in[1];
    const float* N_state  = (const float*)d_in[2];
    const float* m_state  = (const float*)d_in[3];
    float* out = (float*)d_out;

    init_kernel<<<NUM_CW * CDIM / 256, 256>>>(codebook);
    assign_kernel<<<T_TOK / BM, NTHR>>>(x, codebook, out);
    finalize_kernel<<<(NUM_CW * CDIM + 255) / 256, 256>>>(N_state, m_state, out);
}

// round 11
// speedup vs baseline: 1.2827x; 1.2827x over previous
#include <cuda_runtime.h>
#include <cuda_bf16.h>

// Problem constants
#define NUM_CW   512
#define CDIM     64
#define N_IMG    32
#define HWSZ     4096            // 64*64
#define T_TOK    (N_IMG * HWSZ)  // 131072 tokens
#define GAMMA_F  0.99f

// Tiling
#define BM       128             // tokens per block
#define BN       32              // codewords per chunk
#define N_CHUNK  (NUM_CW / BN)   // 16
#define TM       8               // tokens per thread (4 f32x2 pairs)
#define TN       4               // codewords per thread
#define NTHR     128             // (BM/TM)*(BN/TN) = 16*8
#define CS_PAD   40              // row stride for cs (160B, 16B-aligned)

// Output layout: q | codebook_new | N_new | m_new
#define OFF_Q   0
#define OFF_CB  (N_IMG * CDIM * HWSZ)          // 8388608
#define OFF_N   (OFF_CB + NUM_CW * CDIM)       // 8421376
#define OFF_M   (OFF_N + NUM_CW)               // 8421888

// Scratch (device globals; zeroed at load, re-zeroed by finalize each call)
__device__ float g_counts[NUM_CW];
__device__ float g_sums[NUM_CW * CDIM];
__device__ float g_cnorm[NUM_CW];
__device__ float g_cbT[CDIM * NUM_CW];   // codebook transposed: [c][k]

#define FMA_F32X2(acc, a, b) \
    asm("fma.rn.f32x2 %0, %1, %2, %0;" : "+l"(acc) : "l"(a), "l"(b))
#define PACK2(out, lo, hi) \
    asm("mov.b64 %0, {%1, %2};" : "=l"(out) : "f"(lo), "f"(hi))
#define UNPACK2(lo, hi, in) \
    asm("mov.b64 {%0, %1}, %2;" : "=f"(lo), "=f"(hi) : "l"(in))

// Norms (warp-shuffle + atomic) and codebook transpose.
__global__ void init_kernel(const float* __restrict__ codebook) {
    int i = blockIdx.x * blockDim.x + threadIdx.x;  // 0 .. 32767
    float v = codebook[i];
    int k = i >> 6, c = i & 63;
    g_cbT[c * NUM_CW + k] = v;
    float s = v * v;
#pragma unroll
    for (int off = 16; off > 0; off >>= 1)
        s += __shfl_down_sync(0xFFFFFFFFu, s, off);
    if ((threadIdx.x & 31) == 0)
        atomicAdd(&g_cnorm[k], s);
}

// SGEMM-style: x tile and codebook chunk in smem; chunk ch+1 is staged into
// registers during chunk ch's compute (software pipeline), so gmem latency
// is hidden behind FFMA2 work. 5 CTAs/SM (44 KB smem).
__global__ __launch_bounds__(NTHR)
void assign_kernel(const float* __restrict__ x,
                   const float* __restrict__ codebook,
                   float* __restrict__ out) {
    __shared__ __align__(16) float xs[CDIM][BM];      // 32 KB, [c][token]
    __shared__ __align__(16) float cs[CDIM][CS_PAD];  // 10 KB, [c][k-in-chunk]
    __shared__ float snorm[NUM_CW];                   // 2 KB

    const int tid = threadIdx.x;
    const int tx  = tid & 7;          // codeword group 0..7
    const int ty  = tid >> 3;         // token group 0..15
    const int t0  = blockIdx.x * BM;  // first token of block
    const int n   = t0 >> 12;
    const int hw0 = t0 & (HWSZ - 1);
    const long base = (long)n * (CDIM * HWSZ) + hw0;

    // Per-thread chunk-staging coordinates (4 float4 per chunk).
    const int ld_c0 = tid >> 3;              // c for i=0 slot (c = idx>>3)
    const int ld_j  = tid & 7;               // j (float4 col) 0..7

    // Stage chunk 0 while x tile loads are in flight.
    float4 nxt[4];
#pragma unroll
    for (int i = 0; i < 4; i++)
        nxt[i] = *(const float4*)(g_cbT + (ld_c0 + i * 16) * NUM_CW + ld_j * 4);

    // Load x tile: 64 rows of 128 floats, each row contiguous in gmem.
    {
        const float* xsrc = x + base;
#pragma unroll
        for (int i = 0; i < (CDIM * BM / 4) / NTHR; i++) {   // 16 iters
            int idx = tid + i * NTHR;       // 0..2047 float4 slots
            int c = idx >> 5, q4 = idx & 31;
            float4 v = *(const float4*)(xsrc + c * HWSZ + q4 * 4);
            *(float4*)&xs[c][q4 * 4] = v;
        }
#pragma unroll
        for (int i = 0; i < NUM_CW / NTHR; i++)
            snorm[tid + i * NTHR] = g_cnorm[tid + i * NTHR];
    }

    float best_d[TM];
    int   best_k[TM];
#pragma unroll
    for (int m = 0; m < TM; m++) { best_d[m] = 3.4e38f; best_k[m] = 0; }

    for (int ch = 0; ch < N_CHUNK; ch++) {
        __syncthreads();   // cs free (previous compute done) / x tile ready
        // Commit staged chunk ch to smem.
#pragma unroll
        for (int i = 0; i < 4; i++)
            *(float4*)&cs[ld_c0 + i * 16][ld_j * 4] = nxt[i];
        __syncthreads();

        // Stage chunk ch+1 (gmem latency overlaps the compute below).
        if (ch + 1 < N_CHUNK) {
#pragma unroll
            for (int i = 0; i < 4; i++)
                nxt[i] = *(const float4*)(g_cbT + (ld_c0 + i * 16) * NUM_CW +
                                          (ch + 1) * BN + ld_j * 4);
        }

        unsigned long long acc[TM / 2][TN];
#pragma unroll
        for (int p = 0; p < TM / 2; p++)
#pragma unroll
            for (int j = 0; j < TN; j++) acc[p][j] = 0ULL;

#pragma unroll 4
        for (int c = 0; c < CDIM; c++) {
            const ulonglong2* xrow = (const ulonglong2*)&xs[c][ty * TM];
            ulonglong2 xA = xrow[0];   // token pairs (0,1),(2,3)
            ulonglong2 xB = xrow[1];   // token pairs (4,5),(6,7)
            float4 cv = *(const float4*)&cs[c][tx * TN];
            unsigned long long c0, c1, c2, c3;
            PACK2(c0, cv.x, cv.x);
            PACK2(c1, cv.y, cv.y);
            PACK2(c2, cv.z, cv.z);
            PACK2(c3, cv.w, cv.w);
            FMA_F32X2(acc[0][0], xA.x, c0);
            FMA_F32X2(acc[0][1], xA.x, c1);
            FMA_F32X2(acc[0][2], xA.x, c2);
            FMA_F32X2(acc[0][3], xA.x, c3);
            FMA_F32X2(acc[1][0], xA.y, c0);
            FMA_F32X2(acc[1][1], xA.y, c1);
            FMA_F32X2(acc[1][2], xA.y, c2);
            FMA_F32X2(acc[1][3], xA.y, c3);
            FMA_F32X2(acc[2][0], xB.x, c0);
            FMA_F32X2(acc[2][1], xB.x, c1);
            FMA_F32X2(acc[2][2], xB.x, c2);
            FMA_F32X2(acc[2][3], xB.x, c3);
            FMA_F32X2(acc[3][0], xB.y, c0);
            FMA_F32X2(acc[3][1], xB.y, c1);
            FMA_F32X2(acc[3][2], xB.y, c2);
            FMA_F32X2(acc[3][3], xB.y, c3);
        }

        // Update per-token argmin over this chunk's TN codewords.
        int k0 = ch * BN + tx * TN;
#pragma unroll
        for (int j = 0; j < TN; j++) {
            float nrm = snorm[k0 + j];
#pragma unroll
            for (int p = 0; p < TM / 2; p++) {
                float lo, hi;
                UNPACK2(lo, hi, acc[p][j]);
                float d0 = fmaf(-2.0f, lo, nrm);
                float d1 = fmaf(-2.0f, hi, nrm);
                if (d0 < best_d[2 * p])     { best_d[2 * p] = d0;     best_k[2 * p] = k0 + j; }
                if (d1 < best_d[2 * p + 1]) { best_d[2 * p + 1] = d1; best_k[2 * p + 1] = k0 + j; }
            }
        }
    }

    // Cross-tx argmin reduction via packed keys in smem (alias cs).
    __syncthreads();
    unsigned long long* sred = (unsigned long long*)cs;  // [BM][8]
#pragma unroll
    for (int m = 0; m < TM; m++) {
        unsigned int u = __float_as_uint(best_d[m]);
        u = (u & 0x80000000u) ? ~u : (u | 0x80000000u);   // order-preserving
        sred[(ty * TM + m) * 8 + tx] =
            ((unsigned long long)u << 32) | (unsigned int)best_k[m];
    }
    __syncthreads();

    // One thread per token: finish argmin, write q, EMA atomics.
    {
        const int tok = tid;   // 0..127
        unsigned long long best = sred[tok * 8];
#pragma unroll
        for (int i = 1; i < 8; i++) {
            unsigned long long v = sred[tok * 8 + i];
            if (v < best) best = v;
        }
        int bk = (int)(best & 0xFFFFFFFFu);

        atomicAdd(&g_counts[bk], 1.0f);
        const float4* cw4 = (const float4*)(codebook + bk * CDIM);
        float* qo = out + OFF_Q + base + tok;
        float* sums = &g_sums[bk * CDIM];
#pragma unroll
        for (int i = 0; i < CDIM / 4; i++) {
            float4 v = cw4[i];
            qo[(4 * i + 0) * HWSZ] = v.x;
            qo[(4 * i + 1) * HWSZ] = v.y;
            qo[(4 * i + 2) * HWSZ] = v.z;
            qo[(4 * i + 3) * HWSZ] = v.w;
        }
#pragma unroll
        for (int c = 0; c < CDIM; c++)
            atomicAdd(&sums[c], xs[c][tok]);
    }
}

// One thread per (k, c). Also resets scratch for the next call.
__global__ void finalize_kernel(const float* __restrict__ N_state,
                                const float* __restrict__ m_state,
                                float* __restrict__ out) {
    int i = blockIdx.x * blockDim.x + threadIdx.x;
    if (i >= NUM_CW * CDIM) return;
    int k = i / CDIM;
    float cnt = g_counts[k];
    bool occ = cnt > 0.0f;
    float Nold = N_state[k];
    float Nn = occ ? (Nold * GAMMA_F + cnt * (1.0f - GAMMA_F)) : Nold;
    float mold = m_state[i];
    float mn = occ ? (mold * GAMMA_F + g_sums[i] * (1.0f - GAMMA_F)) : mold;
    out[OFF_M + i]  = mn;
    out[OFF_CB + i] = mn / Nn;
    g_sums[i] = 0.0f;
    if ((i % CDIM) == 0) out[OFF_N + k] = Nn;
    if (i < NUM_CW) { g_counts[i] = 0.0f; g_cnorm[i] = 0.0f; }
}

extern "C" void kernel_launch(void* const* d_in, const int* in_sizes, int n_in,
                              void* d_out, int out_size) {
    const float* x        = (const float*)d_in[0];
    const float* codebook = (const float*)d_in[1];
    const float* N_state  = (const float*)d_in[2];
    const float* m_state  = (const float*)d_in[3];
    float* out = (float*)d_out;

    init_kernel<<<NUM_CW * CDIM / 256, 256>>>(codebook);
    assign_kernel<<<T_TOK / BM, NTHR>>>(x, codebook, out);
    finalize_kernel<<<(NUM_CW * CDIM + 255) / 256, 256>>>(N_state, m_state, out);
}